// round 2
// baseline (speedup 1.0000x reference)
#include <cuda_runtime.h>
#include <cuda_bf16.h>

// ---------------- problem constants ----------------
#define MAXN 50000
#define HID  128
#define JKD  384   // 3*HID
#define NOUT 40

// ---------------- device scratch ----------------
__device__ __align__(16) float g_dinv[MAXN];            // degree -> d^-1/2
__device__ __align__(16) float g_h[(long)MAXN * HID];   // dense transform result
__device__ __align__(16) float g_agg[(long)MAXN * HID]; // aggregation buffer
__device__ __align__(16) float g_xs[(long)MAXN * JKD];  // JK concat [x1|x2|x3]

// ---------------- small utility kernels ----------------
__global__ void zero_deg_kernel(int n) {
    int i = blockIdx.x * blockDim.x + threadIdx.x;
    if (i < n) g_dinv[i] = 0.0f;
}

__global__ void deg_kernel(const int* __restrict__ col, int E, int n) {
    int i = blockIdx.x * blockDim.x + threadIdx.x;
    if (i < E) {
        int c = col[i];
        if (c >= 0 && c < n) atomicAdd(&g_dinv[c], 1.0f);
    }
}

__global__ void dinv_kernel(int n) {
    int i = blockIdx.x * blockDim.x + threadIdx.x;
    if (i < n) g_dinv[i] = rsqrtf(g_dinv[i] + 1.0f);  // +1 self loop; deg>=1 always
}

__global__ void zero_agg_kernel(int n128_4) {  // n * 128 / 4 float4s
    int i = blockIdx.x * blockDim.x + threadIdx.x;
    float4* p = (float4*)g_agg;
    if (i < n128_4) p[i] = make_float4(0.f, 0.f, 0.f, 0.f);
}

// ---------------- GEMM: C(g_h)[M x 128] = A[M x K] * B[K x 128] ----------------
// BM=128, BN=128, BK=8, 256 threads, 8x8 per-thread tile.
#define BM 128
#define BN 128
#define BK 8

__global__ __launch_bounds__(256, 2)
void sgemm_kernel(const float* __restrict__ Aext, int a_off_in_xs, int lda,
                  const float* __restrict__ B, int M, int K) {
    const float* A = (a_off_in_xs >= 0) ? (g_xs + a_off_in_xs) : Aext;

    __shared__ __align__(16) float As[BK][BM];
    __shared__ __align__(16) float Bs[BK][BN];

    const int tid = threadIdx.x;
    const int block_row = blockIdx.x * BM;

    const int trow = (tid / 16) * 8;  // 0..120
    const int tcol = (tid % 16) * 8;  // 0..120

    // A tile load mapping: 128 rows x 8 k = 256 float4, one per thread
    const int a_row  = tid >> 1;          // 0..127
    const int a_col4 = (tid & 1) * 4;     // 0 or 4
    // B tile load mapping: 8 rows x 128 cols = 256 float4
    const int b_row = tid >> 5;           // 0..7
    const int b_col = (tid & 31) * 4;     // 0..124

    float acc[8][8];
#pragma unroll
    for (int i = 0; i < 8; i++)
#pragma unroll
        for (int j = 0; j < 8; j++) acc[i][j] = 0.0f;

    for (int k0 = 0; k0 < K; k0 += BK) {
        const int gr = block_row + a_row;
        float4 av = make_float4(0.f, 0.f, 0.f, 0.f);
        if (gr < M) av = *(const float4*)(A + (long)gr * lda + k0 + a_col4);
        As[a_col4 + 0][a_row] = av.x;
        As[a_col4 + 1][a_row] = av.y;
        As[a_col4 + 2][a_row] = av.z;
        As[a_col4 + 3][a_row] = av.w;

        *(float4*)&Bs[b_row][b_col] = *(const float4*)(B + (long)(k0 + b_row) * 128 + b_col);
        __syncthreads();

#pragma unroll
        for (int kk = 0; kk < BK; kk++) {
            float ar[8], br[8];
            *(float4*)(ar)     = *(float4*)&As[kk][trow];
            *(float4*)(ar + 4) = *(float4*)&As[kk][trow + 4];
            *(float4*)(br)     = *(float4*)&Bs[kk][tcol];
            *(float4*)(br + 4) = *(float4*)&Bs[kk][tcol + 4];
#pragma unroll
            for (int i = 0; i < 8; i++)
#pragma unroll
                for (int j = 0; j < 8; j++) acc[i][j] = fmaf(ar[i], br[j], acc[i][j]);
        }
        __syncthreads();
    }

#pragma unroll
    for (int i = 0; i < 8; i++) {
        int r = block_row + trow + i;
        if (r < M) {
            float4 v0 = make_float4(acc[i][0], acc[i][1], acc[i][2], acc[i][3]);
            float4 v1 = make_float4(acc[i][4], acc[i][5], acc[i][6], acc[i][7]);
            *(float4*)&g_h[(long)r * 128 + tcol]     = v0;
            *(float4*)&g_h[(long)r * 128 + tcol + 4] = v1;
        }
    }
}

// ---------------- edge scatter: agg[col] += h[row] * dinv[row]*dinv[col] ----------------
// one warp per edge, float4 gather, 4 scalar atomics per lane (coalesced addresses)
__global__ void scatter_kernel(const int* __restrict__ row,
                               const int* __restrict__ col, int E) {
    int warp = (blockIdx.x * blockDim.x + threadIdx.x) >> 5;
    if (warp >= E) return;
    int lane = threadIdx.x & 31;
    int r = row[warp];
    int c = col[warp];
    float nrm = g_dinv[r] * g_dinv[c];
    float4 v = ((const float4*)g_h)[(long)r * 32 + lane];
    float* dst = &g_agg[(long)c * 128 + lane * 4];
    atomicAdd(dst + 0, v.x * nrm);
    atomicAdd(dst + 1, v.y * nrm);
    atomicAdd(dst + 2, v.z * nrm);
    atomicAdd(dst + 3, v.w * nrm);
}

// ---------------- finalize: xs[:, off:off+128] = relu(agg + h*dinv^2 + b) ----------------
__global__ void finalize_kernel(const float* __restrict__ b, int off, int n) {
    int idx = blockIdx.x * blockDim.x + threadIdx.x;  // over n*32 float4s
    if (idx >= n * 32) return;
    int i = idx >> 5;
    int q = idx & 31;
    float d = g_dinv[i];
    float d2 = d * d;
    float4 a = ((const float4*)g_agg)[idx];
    float4 h = ((const float4*)g_h)[idx];
    float4 bb = ((const float4*)b)[q];
    float4 v;
    v.x = fmaxf(fmaf(h.x, d2, a.x) + bb.x, 0.f);
    v.y = fmaxf(fmaf(h.y, d2, a.y) + bb.y, 0.f);
    v.z = fmaxf(fmaf(h.z, d2, a.z) + bb.z, 0.f);
    v.w = fmaxf(fmaf(h.w, d2, a.w) + bb.w, 0.f);
    *(float4*)&g_xs[(long)i * JKD + off + q * 4] = v;
}

// ---------------- output GEMM: out[M x 40] = xs[M x 384] @ Wout + bout ----------------
// 256 threads = 64 rows x 4 col-groups(10 cols each). K tiled by 16.
__global__ __launch_bounds__(256)
void outgemm_kernel(const float* __restrict__ Wout, const float* __restrict__ bout,
                    float* __restrict__ out, int M) {
    __shared__ float sX[64][17];
    __shared__ __align__(16) float sW[16 * 40];

    const int tid = threadIdx.x;
    const int rowl = tid >> 2;      // 0..63
    const int cg   = tid & 3;       // 0..3 -> cols cg*10..cg*10+9
    const int grow = blockIdx.x * 64 + rowl;

    // X tile load mapping: 64 rows x 16 k = 256 float4
    const int lrow  = tid >> 2;
    const int lcol4 = (tid & 3) * 4;

    float acc[10];
#pragma unroll
    for (int j = 0; j < 10; j++) acc[j] = 0.0f;

    for (int k0 = 0; k0 < JKD; k0 += 16) {
        // load X tile
        int xr = blockIdx.x * 64 + lrow;
        float4 xv = make_float4(0.f, 0.f, 0.f, 0.f);
        if (xr < M) xv = *(const float4*)(g_xs + (long)xr * JKD + k0 + lcol4);
        sX[lrow][lcol4 + 0] = xv.x;
        sX[lrow][lcol4 + 1] = xv.y;
        sX[lrow][lcol4 + 2] = xv.z;
        sX[lrow][lcol4 + 3] = xv.w;
        // load W tile: 16x40 = 640 floats contiguous
        if (tid < 160)
            *(float4*)&sW[tid * 4] = *(const float4*)(Wout + (long)k0 * 40 + tid * 4);
        __syncthreads();

#pragma unroll
        for (int kk = 0; kk < 16; kk++) {
            float a = sX[rowl][kk];
            const float* w = &sW[kk * 40 + cg * 10];
#pragma unroll
            for (int j = 0; j < 10; j++) acc[j] = fmaf(a, w[j], acc[j]);
        }
        __syncthreads();
    }

    if (grow < M) {
#pragma unroll
        for (int j = 0; j < 10; j++)
            out[(long)grow * NOUT + cg * 10 + j] = acc[j] + bout[cg * 10 + j];
    }
}

// ---------------- launch ----------------
extern "C" void kernel_launch(void* const* d_in, const int* in_sizes, int n_in,
                              void* d_out, int out_size) {
    const float* x      = (const float*)d_in[0];
    const int*   ei     = (const int*)d_in[1];   // JAX x64 disabled: int64 -> int32!
    const float* W0 = (const float*)d_in[2];
    const float* b0 = (const float*)d_in[3];
    const float* W1 = (const float*)d_in[4];
    const float* b1 = (const float*)d_in[5];
    const float* W2 = (const float*)d_in[6];
    const float* b2 = (const float*)d_in[7];
    const float* Wout = (const float*)d_in[8];
    const float* bout = (const float*)d_in[9];
    float* out = (float*)d_out;

    const int N = in_sizes[0] / 256;   // feature dim D = 256
    const int E = in_sizes[1] / 2;
    const int* row = ei;
    const int* col = ei + E;

    // ---- gcn_norm ----
    zero_deg_kernel<<<(N + 255) / 256, 256>>>(N);
    deg_kernel<<<(E + 255) / 256, 256>>>(col, E, N);
    dinv_kernel<<<(N + 255) / 256, 256>>>(N);

    const int gemm_grid   = (N + BM - 1) / BM;
    const int zero_grid   = (N * 32 + 255) / 256;
    const int scat_grid   = (int)(((long)E * 32 + 255) / 256);
    const int fin_grid    = (N * 32 + 255) / 256;

    // ---- layer 0 ----
    sgemm_kernel<<<gemm_grid, 256>>>(x, -1, 256, W0, N, 256);
    zero_agg_kernel<<<zero_grid, 256>>>(N * 32);
    scatter_kernel<<<scat_grid, 256>>>(row, col, E);
    finalize_kernel<<<fin_grid, 256>>>(b0, 0, N);

    // ---- layer 1 (reads xs[:,0:128]) ----
    sgemm_kernel<<<gemm_grid, 256>>>(nullptr, 0, JKD, W1, N, 128);
    zero_agg_kernel<<<zero_grid, 256>>>(N * 32);
    scatter_kernel<<<scat_grid, 256>>>(row, col, E);
    finalize_kernel<<<fin_grid, 256>>>(b1, 128, N);

    // ---- layer 2 (reads xs[:,128:256]) ----
    sgemm_kernel<<<gemm_grid, 256>>>(nullptr, 128, JKD, W2, N, 128);
    zero_agg_kernel<<<zero_grid, 256>>>(N * 32);
    scatter_kernel<<<scat_grid, 256>>>(row, col, E);
    finalize_kernel<<<fin_grid, 256>>>(b2, 256, N);

    // ---- JK output ----
    outgemm_kernel<<<(N + 63) / 64, 256>>>(Wout, bout, out, N);
}

// round 3
// speedup vs baseline: 2.0757x; 2.0757x over previous
#include <cuda_runtime.h>
#include <cuda_bf16.h>

// ---------------- problem constants ----------------
#define MAXN 50000
#define MAXE 800000
#define HID  128
#define JKD  384   // 3*HID
#define NOUT 40

// ---------------- device scratch ----------------
__device__ __align__(16) float g_dinv[MAXN];            // degree -> d^-1/2
__device__ __align__(16) float g_h[(long)MAXN * HID];   // dense transform result
__device__ __align__(16) float g_xs[(long)MAXN * JKD];  // JK concat [x1|x2|x3]
__device__ int   g_cnt[MAXN];        // in-degree histogram
__device__ int   g_off[MAXN + 1];    // CSC offsets
__device__ int   g_cur[MAXN];        // fill cursors
__device__ int   g_src[MAXE];        // CSC source node per edge
__device__ float g_wgt[MAXE];        // dinv[src]*dinv[dst] per edge

// ---------------- CSC build ----------------
__global__ void zero_cnt_kernel(int n) {
    int i = blockIdx.x * blockDim.x + threadIdx.x;
    if (i < n) g_cnt[i] = 0;
}

__global__ void hist_kernel(const int* __restrict__ col, int E) {
    int i = blockIdx.x * blockDim.x + threadIdx.x;
    if (i < E) atomicAdd(&g_cnt[col[i]], 1);
}

// single-block exclusive scan over g_cnt -> g_off (4 elems/thread chunks)
__global__ void scan_kernel(int n) {
    __shared__ int ssum[1024];
    __shared__ int scarry;
    int tid = threadIdx.x;
    if (tid == 0) scarry = 0;
    __syncthreads();
    for (int base = 0; base < n; base += 1024 * 4) {
        int idx = base + tid * 4;
        int v[4];
#pragma unroll
        for (int j = 0; j < 4; j++) v[j] = (idx + j < n) ? g_cnt[idx + j] : 0;
        int local = v[0] + v[1] + v[2] + v[3];
        ssum[tid] = local;
        __syncthreads();
#pragma unroll
        for (int d = 1; d < 1024; d <<= 1) {
            int t = (tid >= d) ? ssum[tid - d] : 0;
            __syncthreads();
            ssum[tid] += t;
            __syncthreads();
        }
        int run = scarry + ssum[tid] - local;  // exclusive prefix for this thread
#pragma unroll
        for (int j = 0; j < 4; j++) {
            if (idx + j < n) g_off[idx + j] = run;
            run += v[j];
        }
        __syncthreads();
        if (tid == 1023) scarry += ssum[tid];
        __syncthreads();
    }
    if (tid == 0) g_off[n] = scarry;
}

__global__ void dinv_kernel(int n) {
    int i = blockIdx.x * blockDim.x + threadIdx.x;
    if (i < n) {
        g_dinv[i] = rsqrtf((float)g_cnt[i] + 1.0f);  // +1 self loop
        g_cur[i] = g_off[i];
    }
}

__global__ void reorder_kernel(const int* __restrict__ row,
                               const int* __restrict__ col, int E) {
    int i = blockIdx.x * blockDim.x + threadIdx.x;
    if (i < E) {
        int r = row[i];
        int c = col[i];
        int pos = atomicAdd(&g_cur[c], 1);
        g_src[pos] = r;
        g_wgt[pos] = g_dinv[r] * g_dinv[c];
    }
}

// ---------------- GEMM: C(g_h)[M x 128] = A[M x K] * B[K x 128] ----------------
#define BM 128
#define BN 128
#define BK 8

__global__ __launch_bounds__(256, 2)
void sgemm_kernel(const float* __restrict__ Aext, int a_off_in_xs, int lda,
                  const float* __restrict__ B, int M, int K) {
    const float* A = (a_off_in_xs >= 0) ? (g_xs + a_off_in_xs) : Aext;

    __shared__ __align__(16) float As[BK][BM];
    __shared__ __align__(16) float Bs[BK][BN];

    const int tid = threadIdx.x;
    const int block_row = blockIdx.x * BM;

    const int trow = (tid / 16) * 8;
    const int tcol = (tid % 16) * 8;

    const int a_row  = tid >> 1;
    const int a_col4 = (tid & 1) * 4;
    const int b_row = tid >> 5;
    const int b_col = (tid & 31) * 4;

    float acc[8][8];
#pragma unroll
    for (int i = 0; i < 8; i++)
#pragma unroll
        for (int j = 0; j < 8; j++) acc[i][j] = 0.0f;

    for (int k0 = 0; k0 < K; k0 += BK) {
        const int gr = block_row + a_row;
        float4 av = make_float4(0.f, 0.f, 0.f, 0.f);
        if (gr < M) av = *(const float4*)(A + (long)gr * lda + k0 + a_col4);
        As[a_col4 + 0][a_row] = av.x;
        As[a_col4 + 1][a_row] = av.y;
        As[a_col4 + 2][a_row] = av.z;
        As[a_col4 + 3][a_row] = av.w;

        *(float4*)&Bs[b_row][b_col] = *(const float4*)(B + (long)(k0 + b_row) * 128 + b_col);
        __syncthreads();

#pragma unroll
        for (int kk = 0; kk < BK; kk++) {
            float ar[8], br[8];
            *(float4*)(ar)     = *(float4*)&As[kk][trow];
            *(float4*)(ar + 4) = *(float4*)&As[kk][trow + 4];
            *(float4*)(br)     = *(float4*)&Bs[kk][tcol];
            *(float4*)(br + 4) = *(float4*)&Bs[kk][tcol + 4];
#pragma unroll
            for (int i = 0; i < 8; i++)
#pragma unroll
                for (int j = 0; j < 8; j++) acc[i][j] = fmaf(ar[i], br[j], acc[i][j]);
        }
        __syncthreads();
    }

#pragma unroll
    for (int i = 0; i < 8; i++) {
        int r = block_row + trow + i;
        if (r < M) {
            float4 v0 = make_float4(acc[i][0], acc[i][1], acc[i][2], acc[i][3]);
            float4 v1 = make_float4(acc[i][4], acc[i][5], acc[i][6], acc[i][7]);
            *(float4*)&g_h[(long)r * 128 + tcol]     = v0;
            *(float4*)&g_h[(long)r * 128 + tcol + 4] = v1;
        }
    }
}

// ---------------- gather: xs[c, off:off+128] = relu(sum_in h[r]*w + h[c]*d2 + b) ----------------
// one warp per destination node; lane owns 4 contiguous features (float4)
__global__ __launch_bounds__(256)
void gather_kernel(const float* __restrict__ b, int xs_off, int n) {
    int warp = (blockIdx.x * blockDim.x + threadIdx.x) >> 5;
    if (warp >= n) return;
    int lane = threadIdx.x & 31;
    int c = warp;

    float d = g_dinv[c];
    float d2 = d * d;
    float4 self = ((const float4*)g_h)[(long)c * 32 + lane];
    float4 bb = ((const float4*)b)[lane];
    float4 acc;
    acc.x = fmaf(self.x, d2, bb.x);
    acc.y = fmaf(self.y, d2, bb.y);
    acc.z = fmaf(self.z, d2, bb.z);
    acc.w = fmaf(self.w, d2, bb.w);

    int e = g_off[c];
    const int end = g_off[c + 1];

    for (; e + 4 <= end; e += 4) {
        int r0 = g_src[e + 0], r1 = g_src[e + 1], r2 = g_src[e + 2], r3 = g_src[e + 3];
        float w0 = g_wgt[e + 0], w1 = g_wgt[e + 1], w2 = g_wgt[e + 2], w3 = g_wgt[e + 3];
        float4 v0 = ((const float4*)g_h)[(long)r0 * 32 + lane];
        float4 v1 = ((const float4*)g_h)[(long)r1 * 32 + lane];
        float4 v2 = ((const float4*)g_h)[(long)r2 * 32 + lane];
        float4 v3 = ((const float4*)g_h)[(long)r3 * 32 + lane];
        acc.x = fmaf(v0.x, w0, acc.x); acc.y = fmaf(v0.y, w0, acc.y);
        acc.z = fmaf(v0.z, w0, acc.z); acc.w = fmaf(v0.w, w0, acc.w);
        acc.x = fmaf(v1.x, w1, acc.x); acc.y = fmaf(v1.y, w1, acc.y);
        acc.z = fmaf(v1.z, w1, acc.z); acc.w = fmaf(v1.w, w1, acc.w);
        acc.x = fmaf(v2.x, w2, acc.x); acc.y = fmaf(v2.y, w2, acc.y);
        acc.z = fmaf(v2.z, w2, acc.z); acc.w = fmaf(v2.w, w2, acc.w);
        acc.x = fmaf(v3.x, w3, acc.x); acc.y = fmaf(v3.y, w3, acc.y);
        acc.z = fmaf(v3.z, w3, acc.z); acc.w = fmaf(v3.w, w3, acc.w);
    }
    for (; e < end; e++) {
        int r = g_src[e];
        float w = g_wgt[e];
        float4 v = ((const float4*)g_h)[(long)r * 32 + lane];
        acc.x = fmaf(v.x, w, acc.x); acc.y = fmaf(v.y, w, acc.y);
        acc.z = fmaf(v.z, w, acc.z); acc.w = fmaf(v.w, w, acc.w);
    }

    float4 o;
    o.x = fmaxf(acc.x, 0.f);
    o.y = fmaxf(acc.y, 0.f);
    o.z = fmaxf(acc.z, 0.f);
    o.w = fmaxf(acc.w, 0.f);
    *(float4*)&g_xs[(long)c * JKD + xs_off + lane * 4] = o;
}

// ---------------- output GEMM: out[M x 40] = xs[M x 384] @ Wout + bout ----------------
__global__ __launch_bounds__(256)
void outgemm_kernel(const float* __restrict__ Wout, const float* __restrict__ bout,
                    float* __restrict__ out, int M) {
    __shared__ float sX[64][17];
    __shared__ __align__(16) float sW[16 * 40];

    const int tid = threadIdx.x;
    const int rowl = tid >> 2;
    const int cg   = tid & 3;
    const int grow = blockIdx.x * 64 + rowl;

    const int lrow  = tid >> 2;
    const int lcol4 = (tid & 3) * 4;

    float acc[10];
#pragma unroll
    for (int j = 0; j < 10; j++) acc[j] = 0.0f;

    for (int k0 = 0; k0 < JKD; k0 += 16) {
        int xr = blockIdx.x * 64 + lrow;
        float4 xv = make_float4(0.f, 0.f, 0.f, 0.f);
        if (xr < M) xv = *(const float4*)(g_xs + (long)xr * JKD + k0 + lcol4);
        sX[lrow][lcol4 + 0] = xv.x;
        sX[lrow][lcol4 + 1] = xv.y;
        sX[lrow][lcol4 + 2] = xv.z;
        sX[lrow][lcol4 + 3] = xv.w;
        if (tid < 160)
            *(float4*)&sW[tid * 4] = *(const float4*)(Wout + (long)k0 * 40 + tid * 4);
        __syncthreads();

#pragma unroll
        for (int kk = 0; kk < 16; kk++) {
            float a = sX[rowl][kk];
            const float* w = &sW[kk * 40 + cg * 10];
#pragma unroll
            for (int j = 0; j < 10; j++) acc[j] = fmaf(a, w[j], acc[j]);
        }
        __syncthreads();
    }

    if (grow < M) {
#pragma unroll
        for (int j = 0; j < 10; j++)
            out[(long)grow * NOUT + cg * 10 + j] = acc[j] + bout[cg * 10 + j];
    }
}

// ---------------- launch ----------------
extern "C" void kernel_launch(void* const* d_in, const int* in_sizes, int n_in,
                              void* d_out, int out_size) {
    const float* x      = (const float*)d_in[0];
    const int*   ei     = (const int*)d_in[1];   // int32 (JAX x64 disabled)
    const float* W0 = (const float*)d_in[2];
    const float* b0 = (const float*)d_in[3];
    const float* W1 = (const float*)d_in[4];
    const float* b1 = (const float*)d_in[5];
    const float* W2 = (const float*)d_in[6];
    const float* b2 = (const float*)d_in[7];
    const float* Wout = (const float*)d_in[8];
    const float* bout = (const float*)d_in[9];
    float* out = (float*)d_out;

    const int N = in_sizes[0] / 256;   // feature dim D = 256
    const int E = in_sizes[1] / 2;
    const int* row = ei;
    const int* col = ei + E;

    // ---- CSC build + gcn_norm ----
    zero_cnt_kernel<<<(N + 255) / 256, 256>>>(N);
    hist_kernel<<<(E + 255) / 256, 256>>>(col, E);
    scan_kernel<<<1, 1024>>>(N);
    dinv_kernel<<<(N + 255) / 256, 256>>>(N);
    reorder_kernel<<<(E + 255) / 256, 256>>>(row, col, E);

    const int gemm_grid = (N + BM - 1) / BM;
    const int gat_grid  = (N + 7) / 8;   // 8 warps per 256-thread block

    // ---- layer 0 ----
    sgemm_kernel<<<gemm_grid, 256>>>(x, -1, 256, W0, N, 256);
    gather_kernel<<<gat_grid, 256>>>(b0, 0, N);

    // ---- layer 1 (reads xs[:,0:128]) ----
    sgemm_kernel<<<gemm_grid, 256>>>(nullptr, 0, JKD, W1, N, 128);
    gather_kernel<<<gat_grid, 256>>>(b1, 128, N);

    // ---- layer 2 (reads xs[:,128:256]) ----
    sgemm_kernel<<<gemm_grid, 256>>>(nullptr, 128, JKD, W2, N, 128);
    gather_kernel<<<gat_grid, 256>>>(b2, 256, N);

    // ---- JK output ----
    outgemm_kernel<<<(N + 63) / 64, 256>>>(Wout, bout, out, N);
}